// round 2
// baseline (speedup 1.0000x reference)
#include <cuda_runtime.h>
#include <math.h>

#define NN   100000
#define NE   1600000
#define F    128
#define OUTD 32
#define BN_EPS 1e-5f

// ---------------- scratch (device globals; no allocation allowed) ----------------
__device__ float g_deg[NN];
__device__ float g_inv[NN];
__device__ float g_agg[(size_t)NN * F];
__device__ float g_h[(size_t)NN * F];
__device__ float g_h2[(size_t)NN * F];
__device__ float g_sums[2 * F];   // [0:128) sum, [128:256) sumsq
__device__ float g_bnab[2 * F];   // [0:128) scale a, [128:256) shift b
__device__ float g_m[2 * F];      // [0:128) col-sum(h2), [128:256) edge-weighted sum

// ---------------- zero kernels ----------------
__global__ void k_zero_deg() {
    int i = blockIdx.x * blockDim.x + threadIdx.x;
    int stride = gridDim.x * blockDim.x;
    for (; i < NN; i += stride) g_deg[i] = 0.0f;
}
__global__ void k_zero_agg() {
    size_t i = (size_t)blockIdx.x * blockDim.x + threadIdx.x;
    size_t stride = (size_t)gridDim.x * blockDim.x;
    size_t n4 = (size_t)NN * F / 4;
    float4* p = (float4*)g_agg;
    float4 z = make_float4(0.f, 0.f, 0.f, 0.f);
    for (; i < n4; i += stride) p[i] = z;
}
__global__ void k_zero_sums() {
    int i = threadIdx.x;
    g_sums[i] = 0.0f; g_sums[F + i] = 0.0f;
}
__global__ void k_zero_m() {
    int i = threadIdx.x;
    g_m[i] = 0.0f; g_m[F + i] = 0.0f;
}

// ---------------- degree ----------------
__global__ void k_deg(const int* __restrict__ dst) {
    int i = blockIdx.x * blockDim.x + threadIdx.x;
    int stride = gridDim.x * blockDim.x;
    for (; i < NE; i += stride) atomicAdd(&g_deg[dst[i]], 1.0f);
}
__global__ void k_inv() {
    int i = blockIdx.x * blockDim.x + threadIdx.x;
    int stride = gridDim.x * blockDim.x;
    for (; i < NN; i += stride) g_inv[i] = 1.0f / fmaxf(g_deg[i], 1.0f);
}

// ---------------- scatter: agg[dst] += h[src], warp per edge ----------------
__global__ void k_scatter(const float* __restrict__ h,
                          const int* __restrict__ src,
                          const int* __restrict__ dst) {
    int lane = threadIdx.x & 31;
    int warp = (blockIdx.x * blockDim.x + threadIdx.x) >> 5;
    int nwarp = (gridDim.x * blockDim.x) >> 5;
    for (int e = warp; e < NE; e += nwarp) {
        int s = src[e];
        int d = dst[e];
        float4 v = ((const float4*)(h + (size_t)s * F))[lane];
        float* p = g_agg + (size_t)d * F + lane * 4;
        asm volatile("red.global.add.v4.f32 [%0], {%1,%2,%3,%4};"
                     :: "l"(p), "f"(v.x), "f"(v.y), "f"(v.z), "f"(v.w)
                     : "memory");
    }
}

// ---------------- fused node update: out = [relu](x@Ws + (agg*inv)@Wn + b) ----------------
// 512 threads: j = tid&127 (output feature), grp = tid>>7 selects 4 of 16 staged nodes.
#define NODES_PER_ITER 16
#define SMEM_NODE ((2 * F * F + 2 * NODES_PER_ITER * F) * 4)

__global__ void __launch_bounds__(512, 1)
k_node(const float* __restrict__ x,
       const float* __restrict__ Ws,
       const float* __restrict__ Wn,
       const float* __restrict__ bias,
       float* __restrict__ out,
       int do_relu) {
    extern __shared__ float sm[];
    float* sWs = sm;                 // [128*128], k-major (same as global)
    float* sWn = sm + F * F;
    float* sh  = sm + 2 * F * F;     // [16*128]
    float* sa  = sh + NODES_PER_ITER * F;

    int tid = threadIdx.x;
    for (int i = tid; i < F * F; i += 512) { sWs[i] = Ws[i]; sWn[i] = Wn[i]; }
    __syncthreads();

    int j = tid & 127;
    int grp = tid >> 7;              // 0..3
    float bj = bias[j];

    int stage_node = tid >> 5;       // 0..15 (for staging)
    int stage_c = tid & 31;          // float4 column

    for (int nb = blockIdx.x * NODES_PER_ITER; nb < NN; nb += gridDim.x * NODES_PER_ITER) {
        __syncthreads();  // protect sh/sa from previous iteration's readers
        {
            int gn = nb + stage_node;
            float4 hv = make_float4(0.f, 0.f, 0.f, 0.f);
            float4 av = hv;
            if (gn < NN) {
                hv = ((const float4*)(x + (size_t)gn * F))[stage_c];
                float w = g_inv[gn];
                float4 t = ((const float4*)(g_agg + (size_t)gn * F))[stage_c];
                av = make_float4(t.x * w, t.y * w, t.z * w, t.w * w);
            }
            ((float4*)sh)[tid] = hv;
            ((float4*)sa)[tid] = av;
        }
        __syncthreads();

        float acc[4] = {0.f, 0.f, 0.f, 0.f};
        const float* shb = sh + grp * 4 * F;
        const float* sab = sa + grp * 4 * F;

        #pragma unroll 4
        for (int k0 = 0; k0 < F; k0 += 4) {
            float4 hv[4], av[4];
            #pragma unroll
            for (int t = 0; t < 4; t++) {
                hv[t] = *(const float4*)(shb + t * F + k0);
                av[t] = *(const float4*)(sab + t * F + k0);
            }
            #pragma unroll
            for (int kk = 0; kk < 4; kk++) {
                float ws = sWs[(k0 + kk) * F + j];
                float wn = sWn[(k0 + kk) * F + j];
                #pragma unroll
                for (int t = 0; t < 4; t++) {
                    float hvv = (kk == 0) ? hv[t].x : (kk == 1) ? hv[t].y : (kk == 2) ? hv[t].z : hv[t].w;
                    float avv = (kk == 0) ? av[t].x : (kk == 1) ? av[t].y : (kk == 2) ? av[t].z : av[t].w;
                    acc[t] = fmaf(hvv, ws, acc[t]);
                    acc[t] = fmaf(avv, wn, acc[t]);
                }
            }
        }

        #pragma unroll
        for (int t = 0; t < 4; t++) {
            int gn = nb + grp * 4 + t;
            if (gn < NN) {
                float v = acc[t] + bj;
                if (do_relu) v = fmaxf(v, 0.0f);
                out[(size_t)gn * F + j] = v;
            }
        }
    }
}

// ---------------- batchnorm ----------------
__global__ void k_bnstats(const float* __restrict__ h) {
    int j = threadIdx.x;  // 128
    float s = 0.f, s2 = 0.f;
    for (int n = blockIdx.x; n < NN; n += gridDim.x) {
        float v = h[(size_t)n * F + j];
        s += v; s2 += v * v;
    }
    atomicAdd(&g_sums[j], s);
    atomicAdd(&g_sums[F + j], s2);
}
__global__ void k_bnfin(const float* __restrict__ gamma, const float* __restrict__ beta) {
    int j = threadIdx.x;
    float invN = 1.0f / (float)NN;
    float mu = g_sums[j] * invN;
    float var = g_sums[F + j] * invN - mu * mu;
    float a = gamma[j] * rsqrtf(var + BN_EPS);
    g_bnab[j] = a;
    g_bnab[F + j] = beta[j] - mu * a;
}
__global__ void k_bnapply(float* __restrict__ h) {
    size_t i = (size_t)blockIdx.x * blockDim.x + threadIdx.x;
    size_t stride = (size_t)gridDim.x * blockDim.x;
    size_t n4 = (size_t)NN * (F / 4);
    float4* p = (float4*)h;
    const float4* A = (const float4*)g_bnab;
    const float4* B = (const float4*)(g_bnab + F);
    for (; i < n4; i += stride) {
        float4 v = p[i];
        int c = (int)(i & 31);
        float4 a = A[c], b = B[c];
        v.x = fmaxf(fmaf(v.x, a.x, b.x), 0.f);
        v.y = fmaxf(fmaf(v.y, a.y, b.y), 0.f);
        v.z = fmaxf(fmaf(v.z, a.z, b.z), 0.f);
        v.w = fmaxf(fmaf(v.w, a.w, b.w), 0.f);
        p[i] = v;
    }
}

// ---------------- layer-2 (folded into readout via linearity) ----------------
__global__ void k_colsum(const float* __restrict__ h) {
    int j = threadIdx.x;  // 128
    float s = 0.f;
    for (int n = blockIdx.x; n < NN; n += gridDim.x)
        s += h[(size_t)n * F + j];
    atomicAdd(&g_m[j], s);
}
__global__ void k_edgemean(const float* __restrict__ h,
                           const int* __restrict__ src,
                           const int* __restrict__ dst) {
    int lane = threadIdx.x & 31;
    int warp = (blockIdx.x * blockDim.x + threadIdx.x) >> 5;
    int nwarp = (gridDim.x * blockDim.x) >> 5;
    float4 acc = make_float4(0.f, 0.f, 0.f, 0.f);
    for (int e = warp; e < NE; e += nwarp) {
        int s = src[e];
        float w = g_inv[dst[e]];
        float4 v = ((const float4*)(h + (size_t)s * F))[lane];
        acc.x = fmaf(w, v.x, acc.x);
        acc.y = fmaf(w, v.y, acc.y);
        acc.z = fmaf(w, v.z, acc.z);
        acc.w = fmaf(w, v.w, acc.w);
    }
    float* p = g_m + F + lane * 4;
    atomicAdd(p + 0, acc.x);
    atomicAdd(p + 1, acc.y);
    atomicAdd(p + 2, acc.z);
    atomicAdd(p + 3, acc.w);
}
__global__ void k_final(const float* __restrict__ Ws2,
                        const float* __restrict__ Wn2,
                        const float* __restrict__ b2,
                        float* __restrict__ out) {
    int o = threadIdx.x;  // 32
    float invN = 1.0f / (float)NN;
    float acc = b2[o];
    #pragma unroll 4
    for (int k = 0; k < F; k++) {
        acc = fmaf(g_m[k] * invN, Ws2[k * OUTD + o], acc);
        acc = fmaf(g_m[F + k] * invN, Wn2[k * OUTD + o], acc);
    }
    float m = acc;
    #pragma unroll
    for (int off = 16; off; off >>= 1)
        m = fmaxf(m, __shfl_xor_sync(0xffffffffu, m, off));
    float e = expf(acc - m);
    float s = e;
    #pragma unroll
    for (int off = 16; off; off >>= 1)
        s += __shfl_xor_sync(0xffffffffu, s, off);
    out[o] = e / s;
}

// ---------------- launch ----------------
extern "C" void kernel_launch(void* const* d_in, const int* in_sizes, int n_in,
                              void* d_out, int out_size) {
    const float* feat = (const float*)d_in[0];
    const int*   src  = (const int*)d_in[1];
    const int*   dst  = (const int*)d_in[2];
    const float* Ws0  = (const float*)d_in[3];
    const float* Wn0  = (const float*)d_in[4];
    const float* b0   = (const float*)d_in[5];
    const float* Ws1  = (const float*)d_in[6];
    const float* Wn1  = (const float*)d_in[7];
    const float* b1   = (const float*)d_in[8];
    const float* Ws2  = (const float*)d_in[9];
    const float* Wn2  = (const float*)d_in[10];
    const float* b2   = (const float*)d_in[11];
    const float* g0   = (const float*)d_in[12];
    const float* be0  = (const float*)d_in[13];
    const float* g1   = (const float*)d_in[14];
    const float* be1  = (const float*)d_in[15];
    float* out = (float*)d_out;

    cudaFuncSetAttribute(k_node, cudaFuncAttributeMaxDynamicSharedMemorySize, SMEM_NODE);

    float *h0, *h1;  // device-global scratch addresses
    cudaGetSymbolAddress((void**)&h0, g_h);
    cudaGetSymbolAddress((void**)&h1, g_h2);

    // degree / inverse degree
    k_zero_deg<<<196, 512>>>();
    k_deg<<<2048, 256>>>(dst);
    k_inv<<<196, 512>>>();

    // ---- layer 0 ----
    k_zero_agg<<<4096, 256>>>();
    k_scatter<<<4096, 256>>>(feat, src, dst);
    k_node<<<148, 512, SMEM_NODE>>>(feat, Ws0, Wn0, b0, h0, 1);
    k_zero_sums<<<1, 128>>>();
    k_bnstats<<<1024, 128>>>(h0);
    k_bnfin<<<1, 128>>>(g0, be0);
    k_bnapply<<<2048, 256>>>(h0);

    // ---- layer 1 ----
    k_zero_agg<<<4096, 256>>>();
    k_scatter<<<4096, 256>>>(h0, src, dst);
    k_node<<<148, 512, SMEM_NODE>>>(h0, Ws1, Wn1, b1, h1, 1);
    k_zero_sums<<<1, 128>>>();
    k_bnstats<<<1024, 128>>>(h1);
    k_bnfin<<<1, 128>>>(g1, be1);
    k_bnapply<<<2048, 256>>>(h1);

    // ---- layer 2 folded into readout (mean is linear) ----
    k_zero_m<<<1, 128>>>();
    k_colsum<<<1024, 128>>>(h1);
    k_edgemean<<<2048, 256>>>(h1, src, dst);
    k_final<<<1, 32>>>(Ws2, Wn2, b2, out);
}

// round 3
// speedup vs baseline: 2.4042x; 2.4042x over previous
#include <cuda_runtime.h>
#include <math.h>

#define NN   100000
#define NE   1600000
#define F    128
#define OUTD 32
#define BN_EPS 1e-5f
#define NCHUNK 196   // 196*512 = 100352 >= NN

// ---------------- scratch (device globals; no allocation allowed) ----------------
__device__ int   g_degi[NN];
__device__ float g_inv[NN];
__device__ float g_w[NN];          // w[s] = sum over edges with src==s of inv_deg[dst]
__device__ int   g_off[NN + 1];
__device__ int   g_cur[NN];
__device__ int   g_csr[NE];
__device__ int   g_part[NCHUNK];
__device__ float g_agg[(size_t)NN * F];   // aggregated (already scaled by inv_deg)
__device__ float g_h[(size_t)NN * F];     // layer outputs (pre-BN, post internal relu)
__device__ float g_h2[(size_t)NN * F];
__device__ float g_sums0[2 * F];
__device__ float g_sums1[2 * F];
__device__ float g_ab0[2 * F];     // BN affine: [0:F) scale a, [F:2F) shift b
__device__ float g_ab1[2 * F];
__device__ float g_m[2 * F];       // [0:F) sum t(h1), [F:2F) sum w*t(h1)

// ---------------- init ----------------
__global__ void k_zero() {
    int i = blockIdx.x * blockDim.x + threadIdx.x;
    int stride = gridDim.x * blockDim.x;
    for (; i < NN; i += stride) { g_degi[i] = 0; g_cur[i] = 0; g_w[i] = 0.0f; }
    if (blockIdx.x == 0 && threadIdx.x < 2 * F) {
        g_sums0[threadIdx.x] = 0.0f;
        g_sums1[threadIdx.x] = 0.0f;
        g_m[threadIdx.x] = 0.0f;
    }
}

// ---------------- degree histogram / inverse / src weights ----------------
__global__ void k_hist(const int* __restrict__ dst) {
    int i = blockIdx.x * blockDim.x + threadIdx.x;
    int stride = gridDim.x * blockDim.x;
    for (; i < NE; i += stride) atomicAdd(&g_degi[dst[i]], 1);
}
__global__ void k_inv() {
    int i = blockIdx.x * blockDim.x + threadIdx.x;
    int stride = gridDim.x * blockDim.x;
    for (; i < NN; i += stride) g_inv[i] = 1.0f / fmaxf((float)g_degi[i], 1.0f);
}
__global__ void k_srcw(const int* __restrict__ src, const int* __restrict__ dst) {
    int i = blockIdx.x * blockDim.x + threadIdx.x;
    int stride = gridDim.x * blockDim.x;
    for (; i < NE; i += stride) atomicAdd(&g_w[src[i]], g_inv[dst[i]]);
}

// ---------------- CSR build: scan of degrees, then bucket fill ----------------
__global__ void k_part() {
    __shared__ int sh[512];
    int c = blockIdx.x, t = threadIdx.x;
    int i = c * 512 + t;
    int v = (i < NN) ? g_degi[i] : 0;
    sh[t] = v;
    __syncthreads();
    for (int s = 256; s > 0; s >>= 1) {
        if (t < s) sh[t] += sh[t + s];
        __syncthreads();
    }
    if (t == 0) g_part[c] = sh[0];
}
__global__ void k_scanp() {
    __shared__ int sh[256];
    int t = threadIdx.x;
    sh[t] = (t < NCHUNK) ? g_part[t] : 0;
    __syncthreads();
    for (int d = 1; d < 256; d <<= 1) {
        int v = (t >= d) ? sh[t - d] : 0;
        __syncthreads();
        sh[t] += v;
        __syncthreads();
    }
    if (t < NCHUNK) g_part[t] = (t == 0) ? 0 : sh[t - 1];  // exclusive
    if (t == 0) g_off[NN] = NE;
}
__global__ void k_off() {
    __shared__ int sh[512];
    int c = blockIdx.x, t = threadIdx.x;
    int i = c * 512 + t;
    int v = (i < NN) ? g_degi[i] : 0;
    sh[t] = v;
    __syncthreads();
    for (int d = 1; d < 512; d <<= 1) {
        int u = (t >= d) ? sh[t - d] : 0;
        __syncthreads();
        sh[t] += u;
        __syncthreads();
    }
    if (i < NN) g_off[i] = g_part[c] + (sh[t] - v);
}
__global__ void k_csr(const int* __restrict__ src, const int* __restrict__ dst) {
    int i = blockIdx.x * blockDim.x + threadIdx.x;
    int stride = gridDim.x * blockDim.x;
    for (; i < NE; i += stride) {
        int d = dst[i];
        int p = atomicAdd(&g_cur[d], 1);
        g_csr[g_off[d] + p] = src[i];
    }
}

// ---------------- CSR aggregation: out[n] = inv[n] * sum_{s in N(n)} t(x[s]) ----
// t = identity if xab==null, else relu(a*x+b) (fused BN of previous layer).
__global__ void k_agg(const float* __restrict__ x, const float* __restrict__ xab,
                      float* __restrict__ out) {
    int lane = threadIdx.x & 31;
    int warp = (blockIdx.x * blockDim.x + threadIdx.x) >> 5;
    int nwarp = (gridDim.x * blockDim.x) >> 5;
    float4 a4 = make_float4(1.f, 1.f, 1.f, 1.f);
    float4 b4 = make_float4(0.f, 0.f, 0.f, 0.f);
    if (xab) {
        a4 = ((const float4*)xab)[lane];
        b4 = ((const float4*)(xab + F))[lane];
    }
    for (int n = warp; n < NN; n += nwarp) {
        int e0 = g_off[n], e1 = g_off[n + 1];
        float4 acc = make_float4(0.f, 0.f, 0.f, 0.f);
        for (int e = e0; e < e1; e++) {
            int s = g_csr[e];
            float4 v = ((const float4*)(x + (size_t)s * F))[lane];
            if (xab) {
                v.x = fmaxf(fmaf(v.x, a4.x, b4.x), 0.f);
                v.y = fmaxf(fmaf(v.y, a4.y, b4.y), 0.f);
                v.z = fmaxf(fmaf(v.z, a4.z, b4.z), 0.f);
                v.w = fmaxf(fmaf(v.w, a4.w, b4.w), 0.f);
            }
            acc.x += v.x; acc.y += v.y; acc.z += v.z; acc.w += v.w;
        }
        float w = g_inv[n];
        float4 o = make_float4(acc.x * w, acc.y * w, acc.z * w, acc.w * w);
        ((float4*)(out + (size_t)n * F))[lane] = o;
    }
}

// ---------------- fused node update: out = relu(t(x)@Ws + agg@Wn + b), + BN stats
#define NODES_PER_ITER 16
#define SMEM_NODE ((2 * F * F + 2 * NODES_PER_ITER * F) * 4)

__global__ void __launch_bounds__(512, 1)
k_node(const float* __restrict__ x,
       const float* __restrict__ Ws,
       const float* __restrict__ Wn,
       const float* __restrict__ bias,
       float* __restrict__ out,
       const float* __restrict__ xab,   // BN affine for x (null = identity)
       float* __restrict__ sums) {      // [2F] BN stats accumulator
    extern __shared__ float sm[];
    float* sWs = sm;                 // [128*128], k-major
    float* sWn = sm + F * F;
    float* sh  = sm + 2 * F * F;     // [16*128]
    float* sa  = sh + NODES_PER_ITER * F;

    int tid = threadIdx.x;
    for (int i = tid; i < F * F; i += 512) { sWs[i] = Ws[i]; sWn[i] = Wn[i]; }
    __syncthreads();

    int j = tid & 127;
    int grp = tid >> 7;              // 0..3
    float bj = bias[j];

    int stage_node = tid >> 5;       // 0..15
    int stage_c = tid & 31;          // float4 column

    float4 xa4 = make_float4(1.f, 1.f, 1.f, 1.f);
    float4 xb4 = make_float4(0.f, 0.f, 0.f, 0.f);
    if (xab) {
        xa4 = ((const float4*)xab)[stage_c];
        xb4 = ((const float4*)(xab + F))[stage_c];
    }

    float ls = 0.f, ls2 = 0.f;       // BN stats for feature j

    for (int nb = blockIdx.x * NODES_PER_ITER; nb < NN; nb += gridDim.x * NODES_PER_ITER) {
        __syncthreads();
        {
            int gn = nb + stage_node;
            float4 hv = make_float4(0.f, 0.f, 0.f, 0.f);
            float4 av = hv;
            if (gn < NN) {
                hv = ((const float4*)(x + (size_t)gn * F))[stage_c];
                if (xab) {
                    hv.x = fmaxf(fmaf(hv.x, xa4.x, xb4.x), 0.f);
                    hv.y = fmaxf(fmaf(hv.y, xa4.y, xb4.y), 0.f);
                    hv.z = fmaxf(fmaf(hv.z, xa4.z, xb4.z), 0.f);
                    hv.w = fmaxf(fmaf(hv.w, xa4.w, xb4.w), 0.f);
                }
                av = ((const float4*)(g_agg + (size_t)gn * F))[stage_c];
            }
            ((float4*)sh)[tid] = hv;
            ((float4*)sa)[tid] = av;
        }
        __syncthreads();

        float acc[4] = {0.f, 0.f, 0.f, 0.f};
        const float* shb = sh + grp * 4 * F;
        const float* sab = sa + grp * 4 * F;

        #pragma unroll 4
        for (int k0 = 0; k0 < F; k0 += 4) {
            float4 hv[4], av[4];
            #pragma unroll
            for (int t = 0; t < 4; t++) {
                hv[t] = *(const float4*)(shb + t * F + k0);
                av[t] = *(const float4*)(sab + t * F + k0);
            }
            #pragma unroll
            for (int kk = 0; kk < 4; kk++) {
                float ws = sWs[(k0 + kk) * F + j];
                float wn = sWn[(k0 + kk) * F + j];
                #pragma unroll
                for (int t = 0; t < 4; t++) {
                    float hvv = (kk == 0) ? hv[t].x : (kk == 1) ? hv[t].y : (kk == 2) ? hv[t].z : hv[t].w;
                    float avv = (kk == 0) ? av[t].x : (kk == 1) ? av[t].y : (kk == 2) ? av[t].z : av[t].w;
                    acc[t] = fmaf(hvv, ws, acc[t]);
                    acc[t] = fmaf(avv, wn, acc[t]);
                }
            }
        }

        #pragma unroll
        for (int t = 0; t < 4; t++) {
            int gn = nb + grp * 4 + t;
            if (gn < NN) {
                float v = fmaxf(acc[t] + bj, 0.0f);
                out[(size_t)gn * F + j] = v;
                ls += v;
                ls2 += v * v;
            }
        }
    }

    atomicAdd(&sums[j], ls);
    atomicAdd(&sums[F + j], ls2);
}

// ---------------- batchnorm finalize (compute affine a,b) ----------------
__global__ void k_bnfin(const float* __restrict__ gamma, const float* __restrict__ beta,
                        const float* __restrict__ sums, float* __restrict__ ab) {
    int j = threadIdx.x;
    float invN = 1.0f / (float)NN;
    float mu = sums[j] * invN;
    float var = sums[F + j] * invN - mu * mu;
    float a = gamma[j] * rsqrtf(var + BN_EPS);
    ab[j] = a;
    ab[F + j] = beta[j] - mu * a;
}

// ---------------- final readout: m0 = sum t(h1), m1 = sum w*t(h1) ----------------
__global__ void k_colsum2(const float* __restrict__ h, const float* __restrict__ ab) {
    int j = threadIdx.x;  // 128
    float a = ab[j], b = ab[F + j];
    float s0 = 0.f, s1 = 0.f;
    for (int n = blockIdx.x; n < NN; n += gridDim.x) {
        float v = fmaxf(fmaf(h[(size_t)n * F + j], a, b), 0.f);
        s0 += v;
        s1 += g_w[n] * v;
    }
    atomicAdd(&g_m[j], s0);
    atomicAdd(&g_m[F + j], s1);
}
__global__ void k_final(const float* __restrict__ Ws2,
                        const float* __restrict__ Wn2,
                        const float* __restrict__ b2,
                        float* __restrict__ out) {
    int o = threadIdx.x;  // 32
    float invN = 1.0f / (float)NN;
    float acc = b2[o];
    #pragma unroll 4
    for (int k = 0; k < F; k++) {
        acc = fmaf(g_m[k] * invN, Ws2[k * OUTD + o], acc);
        acc = fmaf(g_m[F + k] * invN, Wn2[k * OUTD + o], acc);
    }
    float m = acc;
    #pragma unroll
    for (int off = 16; off; off >>= 1)
        m = fmaxf(m, __shfl_xor_sync(0xffffffffu, m, off));
    float e = expf(acc - m);
    float s = e;
    #pragma unroll
    for (int off = 16; off; off >>= 1)
        s += __shfl_xor_sync(0xffffffffu, s, off);
    out[o] = e / s;
}

// ---------------- launch ----------------
extern "C" void kernel_launch(void* const* d_in, const int* in_sizes, int n_in,
                              void* d_out, int out_size) {
    const float* feat = (const float*)d_in[0];
    const int*   src  = (const int*)d_in[1];
    const int*   dst  = (const int*)d_in[2];
    const float* Ws0  = (const float*)d_in[3];
    const float* Wn0  = (const float*)d_in[4];
    const float* b0   = (const float*)d_in[5];
    const float* Ws1  = (const float*)d_in[6];
    const float* Wn1  = (const float*)d_in[7];
    const float* b1   = (const float*)d_in[8];
    const float* Ws2  = (const float*)d_in[9];
    const float* Wn2  = (const float*)d_in[10];
    const float* b2   = (const float*)d_in[11];
    const float* g0   = (const float*)d_in[12];
    const float* be0  = (const float*)d_in[13];
    const float* g1   = (const float*)d_in[14];
    const float* be1  = (const float*)d_in[15];
    float* out = (float*)d_out;

    cudaFuncSetAttribute(k_node, cudaFuncAttributeMaxDynamicSharedMemorySize, SMEM_NODE);

    float *h0, *h1, *agg, *s0p, *s1p, *ab0, *ab1;
    cudaGetSymbolAddress((void**)&h0, g_h);
    cudaGetSymbolAddress((void**)&h1, g_h2);
    cudaGetSymbolAddress((void**)&agg, g_agg);
    cudaGetSymbolAddress((void**)&s0p, g_sums0);
    cudaGetSymbolAddress((void**)&s1p, g_sums1);
    cudaGetSymbolAddress((void**)&ab0, g_ab0);
    cudaGetSymbolAddress((void**)&ab1, g_ab1);

    // init + graph preprocessing (CSR + inverse degrees + src weights)
    k_zero<<<196, 512>>>();
    k_hist<<<2048, 256>>>(dst);
    k_inv<<<196, 512>>>();
    k_srcw<<<2048, 256>>>(src, dst);
    k_part<<<NCHUNK, 512>>>();
    k_scanp<<<1, 256>>>();
    k_off<<<NCHUNK, 512>>>();
    k_csr<<<2048, 256>>>(src, dst);

    // ---- layer 0 ----
    k_agg<<<12500, 256>>>(feat, nullptr, agg);
    k_node<<<148, 512, SMEM_NODE>>>(feat, Ws0, Wn0, b0, h0, nullptr, s0p);
    k_bnfin<<<1, 128>>>(g0, be0, s0p, ab0);

    // ---- layer 1 (BN0 fused into readers of h0) ----
    k_agg<<<12500, 256>>>(h0, ab0, agg);
    k_node<<<148, 512, SMEM_NODE>>>(h0, Ws1, Wn1, b1, h1, ab0, s1p);
    k_bnfin<<<1, 128>>>(g1, be1, s1p, ab1);

    // ---- layer 2 folded into readout (mean is linear; BN1 fused here) ----
    k_colsum2<<<1024, 128>>>(h1, ab1);
    k_final<<<1, 32>>>(Ws2, Wn2, b2, out);
}

// round 4
// speedup vs baseline: 4.2261x; 1.7577x over previous
#include <cuda_runtime.h>
#include <cuda_bf16.h>
#include <math.h>

#define NN   100000
#define NE   1600000
#define F    128
#define OUTD 32
#define BN_EPS 1e-5f
#define NCHUNK 196   // 196*512 = 100352 >= NN

// ---------------- scratch (device globals; no allocation allowed) ----------------
__device__ int   g_degi[NN];
__device__ float g_inv[NN];
__device__ float g_w[NN];          // w[s] = sum over edges with src==s of inv_deg[dst]
__device__ int   g_off[NN + 1];
__device__ int   g_cur[NN];
__device__ int   g_csr[NE];
__device__ int   g_part[NCHUNK];
__device__ float g_agg[(size_t)NN * F];   // aggregated (already scaled by inv_deg)
__device__ float g_h[(size_t)NN * F];
__device__ float g_h2[(size_t)NN * F];
__device__ float g_sums0[2 * F];
__device__ float g_sums1[2 * F];
__device__ float g_ab0[2 * F];     // BN affine: [0:F) scale a, [F:2F) shift b
__device__ float g_ab1[2 * F];
__device__ float g_m[2 * F];       // [0:F) sum t(h1), [F:2F) sum w*t(h1)

// ---------------- init ----------------
__global__ void k_zero() {
    int i = blockIdx.x * blockDim.x + threadIdx.x;
    int stride = gridDim.x * blockDim.x;
    for (; i < NN; i += stride) { g_degi[i] = 0; g_cur[i] = 0; g_w[i] = 0.0f; }
    if (blockIdx.x == 0 && threadIdx.x < 2 * F) {
        g_sums0[threadIdx.x] = 0.0f;
        g_sums1[threadIdx.x] = 0.0f;
        g_m[threadIdx.x] = 0.0f;
    }
}

// ---------------- degree histogram / inverse / src weights ----------------
__global__ void k_hist(const int* __restrict__ dst) {
    int i = blockIdx.x * blockDim.x + threadIdx.x;
    int stride = gridDim.x * blockDim.x;
    for (; i < NE; i += stride) atomicAdd(&g_degi[dst[i]], 1);
}
__global__ void k_inv() {
    int i = blockIdx.x * blockDim.x + threadIdx.x;
    int stride = gridDim.x * blockDim.x;
    for (; i < NN; i += stride) g_inv[i] = 1.0f / fmaxf((float)g_degi[i], 1.0f);
}
__global__ void k_srcw(const int* __restrict__ src, const int* __restrict__ dst) {
    int i = blockIdx.x * blockDim.x + threadIdx.x;
    int stride = gridDim.x * blockDim.x;
    for (; i < NE; i += stride) atomicAdd(&g_w[src[i]], g_inv[dst[i]]);
}

// ---------------- CSR build ----------------
__global__ void k_part() {
    __shared__ int sh[512];
    int c = blockIdx.x, t = threadIdx.x;
    int i = c * 512 + t;
    int v = (i < NN) ? g_degi[i] : 0;
    sh[t] = v;
    __syncthreads();
    for (int s = 256; s > 0; s >>= 1) {
        if (t < s) sh[t] += sh[t + s];
        __syncthreads();
    }
    if (t == 0) g_part[c] = sh[0];
}
__global__ void k_scanp() {
    __shared__ int sh[256];
    int t = threadIdx.x;
    sh[t] = (t < NCHUNK) ? g_part[t] : 0;
    __syncthreads();
    for (int d = 1; d < 256; d <<= 1) {
        int v = (t >= d) ? sh[t - d] : 0;
        __syncthreads();
        sh[t] += v;
        __syncthreads();
    }
    if (t < NCHUNK) g_part[t] = (t == 0) ? 0 : sh[t - 1];  // exclusive
    if (t == 0) g_off[NN] = NE;
}
__global__ void k_off() {
    __shared__ int sh[512];
    int c = blockIdx.x, t = threadIdx.x;
    int i = c * 512 + t;
    int v = (i < NN) ? g_degi[i] : 0;
    sh[t] = v;
    __syncthreads();
    for (int d = 1; d < 512; d <<= 1) {
        int u = (t >= d) ? sh[t - d] : 0;
        __syncthreads();
        sh[t] += u;
        __syncthreads();
    }
    if (i < NN) g_off[i] = g_part[c] + (sh[t] - v);
}
__global__ void k_csr(const int* __restrict__ src, const int* __restrict__ dst) {
    int i = blockIdx.x * blockDim.x + threadIdx.x;
    int stride = gridDim.x * blockDim.x;
    for (; i < NE; i += stride) {
        int d = dst[i];
        int p = atomicAdd(&g_cur[d], 1);
        g_csr[g_off[d] + p] = src[i];
    }
}

// ---------------- CSR aggregation ----------------
__global__ void k_agg(const float* __restrict__ x, const float* __restrict__ xab,
                      float* __restrict__ out) {
    int lane = threadIdx.x & 31;
    int warp = (blockIdx.x * blockDim.x + threadIdx.x) >> 5;
    int nwarp = (gridDim.x * blockDim.x) >> 5;
    float4 a4 = make_float4(1.f, 1.f, 1.f, 1.f);
    float4 b4 = make_float4(0.f, 0.f, 0.f, 0.f);
    if (xab) {
        a4 = ((const float4*)xab)[lane];
        b4 = ((const float4*)(xab + F))[lane];
    }
    for (int n = warp; n < NN; n += nwarp) {
        int e0 = g_off[n], e1 = g_off[n + 1];
        float4 acc = make_float4(0.f, 0.f, 0.f, 0.f);
        for (int e = e0; e < e1; e++) {
            int s = g_csr[e];
            float4 v = ((const float4*)(x + (size_t)s * F))[lane];
            if (xab) {
                v.x = fmaxf(fmaf(v.x, a4.x, b4.x), 0.f);
                v.y = fmaxf(fmaf(v.y, a4.y, b4.y), 0.f);
                v.z = fmaxf(fmaf(v.z, a4.z, b4.z), 0.f);
                v.w = fmaxf(fmaf(v.w, a4.w, b4.w), 0.f);
            }
            acc.x += v.x; acc.y += v.y; acc.z += v.z; acc.w += v.w;
        }
        float w = g_inv[n];
        float4 o = make_float4(acc.x * w, acc.y * w, acc.z * w, acc.w * w);
        ((float4*)(out + (size_t)n * F))[lane] = o;
    }
}

// ================= tensor-core node update ==============================
// C[64 x 128] = X[64 x 256] @ W[256 x 128],  X = [t(x) | agg],  W = [Ws; Wn]
// split-bf16: v = hi + lo; product = hiX*hiW + hiX*loW + loX*hiW (err ~2^-17)
// smem words (uint32):
//   wW_hi [128][136]  (word kp = packed k pair {2kp, 2kp+1})
//   wW_lo [128][136]
//   sA_hi [64][132]   (row-major bf16 pairs)
//   sA_lo [64][132]
#define WW_STRIDE 136
#define SA_STRIDE 132
#define OFF_WLO  (128 * WW_STRIDE)
#define OFF_AHI  (2 * 128 * WW_STRIDE)
#define OFF_ALO  (2 * 128 * WW_STRIDE + 64 * SA_STRIDE)
#define SMEM_WORDS (2 * 128 * WW_STRIDE + 2 * 64 * SA_STRIDE)
#define SMEM_NODE (SMEM_WORDS * 4)
#define NTILES ((NN + 63) / 64)

__device__ __forceinline__ void cvt_pair(float vx, float vy, unsigned& hi, unsigned& lo) {
    __nv_bfloat16 hx = __float2bfloat16(vx);
    __nv_bfloat16 hy = __float2bfloat16(vy);
    __nv_bfloat16 lx = __float2bfloat16(vx - __bfloat162float(hx));
    __nv_bfloat16 ly = __float2bfloat16(vy - __bfloat162float(hy));
    hi = (unsigned)__bfloat16_as_ushort(hx) | ((unsigned)__bfloat16_as_ushort(hy) << 16);
    lo = (unsigned)__bfloat16_as_ushort(lx) | ((unsigned)__bfloat16_as_ushort(ly) << 16);
}

__device__ __forceinline__ void mma_bf16(float* c, unsigned a0, unsigned a1, unsigned a2,
                                         unsigned a3, unsigned b0, unsigned b1) {
    asm volatile(
        "mma.sync.aligned.m16n8k16.row.col.f32.bf16.bf16.f32 "
        "{%0,%1,%2,%3}, {%4,%5,%6,%7}, {%8,%9}, {%0,%1,%2,%3};"
        : "+f"(c[0]), "+f"(c[1]), "+f"(c[2]), "+f"(c[3])
        : "r"(a0), "r"(a1), "r"(a2), "r"(a3), "r"(b0), "r"(b1));
}

__global__ void __launch_bounds__(512, 1)
k_node(const float* __restrict__ x,
       const float* __restrict__ Ws,
       const float* __restrict__ Wn,
       const float* __restrict__ bias,
       float* __restrict__ out,
       const float* __restrict__ xab,   // BN affine for x (null = identity)
       float* __restrict__ sums) {      // [2F] BN stats accumulator
    extern __shared__ unsigned sm[];
    unsigned* wW_hi = sm;
    unsigned* wW_lo = sm + OFF_WLO;
    unsigned* sA_hi = sm + OFF_AHI;
    unsigned* sA_lo = sm + OFF_ALO;

    int tid = threadIdx.x;
    int lane = tid & 31;
    int wid = tid >> 5;            // 0..15
    int warpM = wid >> 2;          // 0..3 -> rows warpM*16
    int warpN = wid & 3;           // 0..3 -> cols warpN*32
    int g = lane >> 2;             // 0..7
    int tg = lane & 3;             // 0..3

    // ---- stage W (hi/lo, k-pair packed) ----
    for (int idx = tid; idx < 128 * 128; idx += 512) {
        int kp = idx >> 7, n = idx & 127;
        int k0 = kp * 2, k1 = k0 + 1;
        float w0 = (k0 < F) ? Ws[k0 * F + n] : Wn[(k0 - F) * F + n];
        float w1 = (k1 < F) ? Ws[k1 * F + n] : Wn[(k1 - F) * F + n];
        unsigned hi, lo;
        cvt_pair(w0, w1, hi, lo);
        wW_hi[kp * WW_STRIDE + n] = hi;
        wW_lo[kp * WW_STRIDE + n] = lo;
    }

    // staging role
    int sr = tid >> 3;            // row 0..63
    int cb = tid & 7;             // 32-col block

    float ls[8], ls2[8];
    #pragma unroll
    for (int i = 0; i < 8; i++) { ls[i] = 0.f; ls2[i] = 0.f; }

    // bias for this thread's 8 columns
    float bcol[8];
    #pragma unroll
    for (int nt = 0; nt < 4; nt++) {
        int col = warpN * 32 + nt * 8 + tg * 2;
        bcol[nt * 2 + 0] = bias[col];
        bcol[nt * 2 + 1] = bias[col + 1];
    }

    for (int tile = blockIdx.x; tile < NTILES; tile += gridDim.x) {
        int nb = tile * 64;
        __syncthreads();   // protect previous tile's A reads (also covers W stage 1st time)

        // ---- stage X tile (convert to split bf16) ----
        {
            int gn = nb + sr;
            unsigned* dhi = sA_hi + sr * SA_STRIDE + cb * 16;
            unsigned* dlo = sA_lo + sr * SA_STRIDE + cb * 16;
            if (gn < NN) {
                if (cb < 4) {
                    const float4* px = (const float4*)(x + (size_t)gn * F) + cb * 8;
                    #pragma unroll
                    for (int i = 0; i < 8; i++) {
                        float4 v = px[i];
                        if (xab) {
                            float4 a4 = ((const float4*)xab)[cb * 8 + i];
                            float4 b4 = ((const float4*)(xab + F))[cb * 8 + i];
                            v.x = fmaxf(fmaf(v.x, a4.x, b4.x), 0.f);
                            v.y = fmaxf(fmaf(v.y, a4.y, b4.y), 0.f);
                            v.z = fmaxf(fmaf(v.z, a4.z, b4.z), 0.f);
                            v.w = fmaxf(fmaf(v.w, a4.w, b4.w), 0.f);
                        }
                        unsigned h0, l0, h1, l1;
                        cvt_pair(v.x, v.y, h0, l0);
                        cvt_pair(v.z, v.w, h1, l1);
                        dhi[i * 2] = h0; dhi[i * 2 + 1] = h1;
                        dlo[i * 2] = l0; dlo[i * 2 + 1] = l1;
                    }
                } else {
                    const float4* pa = (const float4*)(g_agg + (size_t)gn * F) + (cb - 4) * 8;
                    #pragma unroll
                    for (int i = 0; i < 8; i++) {
                        float4 v = pa[i];
                        unsigned h0, l0, h1, l1;
                        cvt_pair(v.x, v.y, h0, l0);
                        cvt_pair(v.z, v.w, h1, l1);
                        dhi[i * 2] = h0; dhi[i * 2 + 1] = h1;
                        dlo[i * 2] = l0; dlo[i * 2 + 1] = l1;
                    }
                }
            } else {
                #pragma unroll
                for (int i = 0; i < 16; i++) { dhi[i] = 0u; dlo[i] = 0u; }
            }
        }
        __syncthreads();

        // ---- mma main loop ----
        float c[4][4];
        #pragma unroll
        for (int nt = 0; nt < 4; nt++)
            #pragma unroll
            for (int q = 0; q < 4; q++) c[nt][q] = 0.f;

        int rbase = (warpM * 16 + g) * SA_STRIDE;
        #pragma unroll 4
        for (int s = 0; s < 16; s++) {
            int ai = rbase + s * 8 + tg;
            unsigned a0h = sA_hi[ai];
            unsigned a1h = sA_hi[ai + 8 * SA_STRIDE];
            unsigned a2h = sA_hi[ai + 4];
            unsigned a3h = sA_hi[ai + 8 * SA_STRIDE + 4];
            unsigned a0l = sA_lo[ai];
            unsigned a1l = sA_lo[ai + 8 * SA_STRIDE];
            unsigned a2l = sA_lo[ai + 4];
            unsigned a3l = sA_lo[ai + 8 * SA_STRIDE + 4];
            int bi = (s * 8 + tg) * WW_STRIDE + warpN * 32 + g;
            #pragma unroll
            for (int nt = 0; nt < 4; nt++) {
                unsigned b0h = wW_hi[bi + nt * 8];
                unsigned b1h = wW_hi[bi + 4 * WW_STRIDE + nt * 8];
                unsigned b0l = wW_lo[bi + nt * 8];
                unsigned b1l = wW_lo[bi + 4 * WW_STRIDE + nt * 8];
                mma_bf16(c[nt], a0h, a1h, a2h, a3h, b0h, b1h);
                mma_bf16(c[nt], a0h, a1h, a2h, a3h, b0l, b1l);
                mma_bf16(c[nt], a0l, a1l, a2l, a3l, b0h, b1h);
            }
        }

        // ---- epilogue: bias + relu + store + BN stats ----
        int r0 = nb + warpM * 16 + g;
        int r1 = r0 + 8;
        #pragma unroll
        for (int nt = 0; nt < 4; nt++) {
            int col = warpN * 32 + nt * 8 + tg * 2;
            float v0 = fmaxf(c[nt][0] + bcol[nt * 2], 0.f);
            float v1 = fmaxf(c[nt][1] + bcol[nt * 2 + 1], 0.f);
            float v2 = fmaxf(c[nt][2] + bcol[nt * 2], 0.f);
            float v3 = fmaxf(c[nt][3] + bcol[nt * 2 + 1], 0.f);
            if (r0 < NN) {
                *(float2*)(out + (size_t)r0 * F + col) = make_float2(v0, v1);
                ls[nt * 2] += v0;  ls2[nt * 2] += v0 * v0;
                ls[nt * 2 + 1] += v1; ls2[nt * 2 + 1] += v1 * v1;
            }
            if (r1 < NN) {
                *(float2*)(out + (size_t)r1 * F + col) = make_float2(v2, v3);
                ls[nt * 2] += v2;  ls2[nt * 2] += v2 * v2;
                ls[nt * 2 + 1] += v3; ls2[nt * 2 + 1] += v3 * v3;
            }
        }
    }

    // ---- BN stats: smem reduce then one global atomic per column ----
    __syncthreads();
    float* red = (float*)sA_hi;    // reuse: 256 floats
    for (int i = tid; i < 2 * F; i += 512) red[i] = 0.f;
    __syncthreads();
    #pragma unroll
    for (int nt = 0; nt < 4; nt++) {
        int col = warpN * 32 + nt * 8 + tg * 2;
        atomicAdd(&red[col], ls[nt * 2]);
        atomicAdd(&red[col + 1], ls[nt * 2 + 1]);
        atomicAdd(&red[F + col], ls2[nt * 2]);
        atomicAdd(&red[F + col + 1], ls2[nt * 2 + 1]);
    }
    __syncthreads();
    if (tid < 2 * F) atomicAdd(&sums[tid], red[tid]);
}

// ---------------- batchnorm finalize ----------------
__global__ void k_bnfin(const float* __restrict__ gamma, const float* __restrict__ beta,
                        const float* __restrict__ sums, float* __restrict__ ab) {
    int j = threadIdx.x;
    float invN = 1.0f / (float)NN;
    float mu = sums[j] * invN;
    float var = sums[F + j] * invN - mu * mu;
    float a = gamma[j] * rsqrtf(var + BN_EPS);
    ab[j] = a;
    ab[F + j] = beta[j] - mu * a;
}

// ---------------- final readout ----------------
__global__ void k_colsum2(const float* __restrict__ h, const float* __restrict__ ab) {
    int j = threadIdx.x;  // 128
    float a = ab[j], b = ab[F + j];
    float s0 = 0.f, s1 = 0.f;
    for (int n = blockIdx.x; n < NN; n += gridDim.x) {
        float v = fmaxf(fmaf(h[(size_t)n * F + j], a, b), 0.f);
        s0 += v;
        s1 += g_w[n] * v;
    }
    atomicAdd(&g_m[j], s0);
    atomicAdd(&g_m[F + j], s1);
}
__global__ void k_final(const float* __restrict__ Ws2,
                        const float* __restrict__ Wn2,
                        const float* __restrict__ b2,
                        float* __restrict__ out) {
    int o = threadIdx.x;  // 32
    float invN = 1.0f / (float)NN;
    float acc = b2[o];
    #pragma unroll 4
    for (int k = 0; k < F; k++) {
        acc = fmaf(g_m[k] * invN, Ws2[k * OUTD + o], acc);
        acc = fmaf(g_m[F + k] * invN, Wn2[k * OUTD + o], acc);
    }
    float m = acc;
    #pragma unroll
    for (int off = 16; off; off >>= 1)
        m = fmaxf(m, __shfl_xor_sync(0xffffffffu, m, off));
    float e = expf(acc - m);
    float s = e;
    #pragma unroll
    for (int off = 16; off; off >>= 1)
        s += __shfl_xor_sync(0xffffffffu, s, off);
    out[o] = e / s;
}

// ---------------- launch ----------------
extern "C" void kernel_launch(void* const* d_in, const int* in_sizes, int n_in,
                              void* d_out, int out_size) {
    const float* feat = (const float*)d_in[0];
    const int*   src  = (const int*)d_in[1];
    const int*   dst  = (const int*)d_in[2];
    const float* Ws0  = (const float*)d_in[3];
    const float* Wn0  = (const float*)d_in[4];
    const float* b0   = (const float*)d_in[5];
    const float* Ws1  = (const float*)d_in[6];
    const float* Wn1  = (const float*)d_in[7];
    const float* b1   = (const float*)d_in[8];
    const float* Ws2  = (const float*)d_in[9];
    const float* Wn2  = (const float*)d_in[10];
    const float* b2   = (const float*)d_in[11];
    const float* g0   = (const float*)d_in[12];
    const float* be0  = (const float*)d_in[13];
    const float* g1   = (const float*)d_in[14];
    const float* be1  = (const float*)d_in[15];
    float* out = (float*)d_out;

    cudaFuncSetAttribute(k_node, cudaFuncAttributeMaxDynamicSharedMemorySize, SMEM_NODE);

    float *h0, *h1, *agg, *s0p, *s1p, *ab0, *ab1;
    cudaGetSymbolAddress((void**)&h0, g_h);
    cudaGetSymbolAddress((void**)&h1, g_h2);
    cudaGetSymbolAddress((void**)&agg, g_agg);
    cudaGetSymbolAddress((void**)&s0p, g_sums0);
    cudaGetSymbolAddress((void**)&s1p, g_sums1);
    cudaGetSymbolAddress((void**)&ab0, g_ab0);
    cudaGetSymbolAddress((void**)&ab1, g_ab1);

    // init + graph preprocessing
    k_zero<<<196, 512>>>();
    k_hist<<<2048, 256>>>(dst);
    k_inv<<<196, 512>>>();
    k_srcw<<<2048, 256>>>(src, dst);
    k_part<<<NCHUNK, 512>>>();
    k_scanp<<<1, 256>>>();
    k_off<<<NCHUNK, 512>>>();
    k_csr<<<2048, 256>>>(src, dst);

    // ---- layer 0 ----
    k_agg<<<12500, 256>>>(feat, nullptr, agg);
    k_node<<<148, 512, SMEM_NODE>>>(feat, Ws0, Wn0, b0, h0, nullptr, s0p);
    k_bnfin<<<1, 128>>>(g0, be0, s0p, ab0);

    // ---- layer 1 (BN0 fused into readers of h0) ----
    k_agg<<<12500, 256>>>(h0, ab0, agg);
    k_node<<<148, 512, SMEM_NODE>>>(h0, Ws1, Wn1, b1, h1, ab0, s1p);
    k_bnfin<<<1, 128>>>(g1, be1, s1p, ab1);

    // ---- layer 2 folded into readout ----
    k_colsum2<<<1024, 128>>>(h1, ab1);
    k_final<<<1, 32>>>(Ws2, Wn2, b2, out);
}

// round 6
// speedup vs baseline: 5.2736x; 1.2479x over previous
#include <cuda_runtime.h>
#include <cuda_bf16.h>
#include <math.h>

#define NN   100000
#define NE   1600000
#define F    128
#define OUTD 32
#define BN_EPS 1e-5f
#define NCHUNK 196   // 196*512 = 100352 >= NN

// ---------------- scratch (device globals; no allocation allowed) ----------------
__device__ int   g_degi[NN];
__device__ float g_inv[NN];
__device__ float g_w[NN];          // w[s] = sum over edges with src==s of inv_deg[dst]
__device__ int   g_off[NN + 1];
__device__ int   g_cur[NN];
__device__ int   g_csr[NE];
__device__ int   g_part[NCHUNK];
__device__ float g_agg[(size_t)NN * F];          // aggregated fp32 (scaled by inv_deg)
__device__ __nv_bfloat16 g_xb[(size_t)NN * F];   // bf16 features
__device__ __nv_bfloat16 g_hb0[(size_t)NN * F];  // bf16 layer outputs
__device__ __nv_bfloat16 g_hb1[(size_t)NN * F];
__device__ float g_sums0[2 * F];
__device__ float g_sums1[2 * F];
__device__ float g_ab0[2 * F];     // BN affine: [0:F) scale a, [F:2F) shift b
__device__ float g_ab1[2 * F];
__device__ float g_m[2 * F];       // [0:F) sum t(h1), [F:2F) sum w*t(h1)

__device__ __forceinline__ float bflo(unsigned w) { return __uint_as_float(w << 16); }
__device__ __forceinline__ float bfhi(unsigned w) { return __uint_as_float(w & 0xffff0000u); }

// ---------------- init ----------------
__global__ void k_zero() {
    int i = blockIdx.x * blockDim.x + threadIdx.x;
    int stride = gridDim.x * blockDim.x;
    for (; i < NN; i += stride) { g_degi[i] = 0; g_cur[i] = 0; g_w[i] = 0.0f; }
    if (blockIdx.x == 0 && threadIdx.x < 2 * F) {
        g_sums0[threadIdx.x] = 0.0f;
        g_sums1[threadIdx.x] = 0.0f;
        g_m[threadIdx.x] = 0.0f;
    }
}

// ---------------- fused: degree histogram + feat->bf16 conversion ----------------
#define HIST_BLOCKS 2048
#define CVT_BLOCKS  1552
__global__ void k_histcvt(const int* __restrict__ dst, const float* __restrict__ feat) {
    if (blockIdx.x < HIST_BLOCKS) {
        int i = blockIdx.x * 256 + threadIdx.x;
        int stride = HIST_BLOCKS * 256;
        for (; i < NE; i += stride) atomicAdd(&g_degi[dst[i]], 1);
    } else {
        size_t i = (size_t)(blockIdx.x - HIST_BLOCKS) * 256 + threadIdx.x;
        size_t stride = (size_t)CVT_BLOCKS * 256;
        size_t np = (size_t)NN * F / 2;
        const float2* src2 = (const float2*)feat;
        __nv_bfloat162* dst2 = (__nv_bfloat162*)g_xb;
        for (; i < np; i += stride) {
            float2 v = src2[i];
            dst2[i] = __floats2bfloat162_rn(v.x, v.y);
        }
    }
}

__global__ void k_inv() {
    int i = blockIdx.x * blockDim.x + threadIdx.x;
    int stride = gridDim.x * blockDim.x;
    for (; i < NN; i += stride) g_inv[i] = 1.0f / fmaxf((float)g_degi[i], 1.0f);
}

// ---------------- CSR build ----------------
__global__ void k_part() {
    __shared__ int sh[512];
    int c = blockIdx.x, t = threadIdx.x;
    int i = c * 512 + t;
    int v = (i < NN) ? g_degi[i] : 0;
    sh[t] = v;
    __syncthreads();
    for (int s = 256; s > 0; s >>= 1) {
        if (t < s) sh[t] += sh[t + s];
        __syncthreads();
    }
    if (t == 0) g_part[c] = sh[0];
}
__global__ void k_scanp() {
    __shared__ int sh[256];
    int t = threadIdx.x;
    sh[t] = (t < NCHUNK) ? g_part[t] : 0;
    __syncthreads();
    for (int d = 1; d < 256; d <<= 1) {
        int v = (t >= d) ? sh[t - d] : 0;
        __syncthreads();
        sh[t] += v;
        __syncthreads();
    }
    if (t < NCHUNK) g_part[t] = (t == 0) ? 0 : sh[t - 1];  // exclusive
    if (t == 0) g_off[NN] = NE;
}
__global__ void k_off() {
    __shared__ int sh[512];
    int c = blockIdx.x, t = threadIdx.x;
    int i = c * 512 + t;
    int v = (i < NN) ? g_degi[i] : 0;
    sh[t] = v;
    __syncthreads();
    for (int d = 1; d < 512; d <<= 1) {
        int u = (t >= d) ? sh[t - d] : 0;
        __syncthreads();
        sh[t] += u;
        __syncthreads();
    }
    if (i < NN) g_off[i] = g_part[c] + (sh[t] - v);
}
// merged CSR fill + src-weight accumulation (one edge pass)
__global__ void k_csrw(const int* __restrict__ src, const int* __restrict__ dst) {
    int i = blockIdx.x * blockDim.x + threadIdx.x;
    int stride = gridDim.x * blockDim.x;
    for (; i < NE; i += stride) {
        int d = dst[i];
        int s = src[i];
        float iv = g_inv[d];
        int p = atomicAdd(&g_cur[d], 1);
        g_csr[g_off[d] + p] = s;
        atomicAdd(&g_w[s], iv);
    }
}

// ---------------- CSR aggregation: out[n] = inv[n] * sum bf16 x[s] ----------------
__global__ void k_agg(const __nv_bfloat16* __restrict__ x, float* __restrict__ out) {
    int lane = threadIdx.x & 31;
    int warp = (blockIdx.x * blockDim.x + threadIdx.x) >> 5;
    int nwarp = (gridDim.x * blockDim.x) >> 5;
    for (int n = warp; n < NN; n += nwarp) {
        int e0 = g_off[n], e1 = g_off[n + 1];
        float4 acc = make_float4(0.f, 0.f, 0.f, 0.f);
        int e = e0;
        for (; e + 1 < e1; e += 2) {
            int s0 = g_csr[e], s1 = g_csr[e + 1];
            uint2 v0 = ((const uint2*)(x + (size_t)s0 * F))[lane];
            uint2 v1 = ((const uint2*)(x + (size_t)s1 * F))[lane];
            acc.x += bflo(v0.x) + bflo(v1.x);
            acc.y += bfhi(v0.x) + bfhi(v1.x);
            acc.z += bflo(v0.y) + bflo(v1.y);
            acc.w += bfhi(v0.y) + bfhi(v1.y);
        }
        if (e < e1) {
            int s0 = g_csr[e];
            uint2 v0 = ((const uint2*)(x + (size_t)s0 * F))[lane];
            acc.x += bflo(v0.x); acc.y += bfhi(v0.x);
            acc.z += bflo(v0.y); acc.w += bfhi(v0.y);
        }
        float w = g_inv[n];
        float4 o = make_float4(acc.x * w, acc.y * w, acc.z * w, acc.w * w);
        ((float4*)(out + (size_t)n * F))[lane] = o;
    }
}

// ================= tensor-core node update ==============================
// C[64 x 128] = X[64 x 256] @ W[256 x 128],  X = [x_bf16 | agg_fp32],  W = [Ws; Wn]
// weights split-bf16 (hi+lo); x half has lo==0 -> loA*hiW mma only for k>=128.
#define WW_STRIDE 136
#define SA_STRIDE 132
#define OFF_WLO  (128 * WW_STRIDE)
#define OFF_AHI  (2 * 128 * WW_STRIDE)
#define OFF_ALO  (2 * 128 * WW_STRIDE + 64 * SA_STRIDE)
#define SMEM_WORDS (2 * 128 * WW_STRIDE + 2 * 64 * SA_STRIDE)
#define SMEM_NODE (SMEM_WORDS * 4)
#define NTILES ((NN + 63) / 64)

__device__ __forceinline__ void cvt_pair(float vx, float vy, unsigned& hi, unsigned& lo) {
    __nv_bfloat16 hx = __float2bfloat16(vx);
    __nv_bfloat16 hy = __float2bfloat16(vy);
    __nv_bfloat16 lx = __float2bfloat16(vx - __bfloat162float(hx));
    __nv_bfloat16 ly = __float2bfloat16(vy - __bfloat162float(hy));
    hi = (unsigned)__bfloat16_as_ushort(hx) | ((unsigned)__bfloat16_as_ushort(hy) << 16);
    lo = (unsigned)__bfloat16_as_ushort(lx) | ((unsigned)__bfloat16_as_ushort(ly) << 16);
}

__device__ __forceinline__ void mma_bf16(float* c, unsigned a0, unsigned a1, unsigned a2,
                                         unsigned a3, unsigned b0, unsigned b1) {
    asm volatile(
        "mma.sync.aligned.m16n8k16.row.col.f32.bf16.bf16.f32 "
        "{%0,%1,%2,%3}, {%4,%5,%6,%7}, {%8,%9}, {%0,%1,%2,%3};"
        : "+f"(c[0]), "+f"(c[1]), "+f"(c[2]), "+f"(c[3])
        : "r"(a0), "r"(a1), "r"(a2), "r"(a3), "r"(b0), "r"(b1));
}

__global__ void __launch_bounds__(512, 1)
k_node(const __nv_bfloat16* __restrict__ x,
       const float* __restrict__ Ws,
       const float* __restrict__ Wn,
       const float* __restrict__ bias,
       __nv_bfloat16* __restrict__ out,
       float* __restrict__ sums) {      // [2F] BN stats accumulator
    extern __shared__ unsigned sm[];
    unsigned* wW_hi = sm;
    unsigned* wW_lo = sm + OFF_WLO;
    unsigned* sA_hi = sm + OFF_AHI;
    unsigned* sA_lo = sm + OFF_ALO;

    int tid = threadIdx.x;
    int lane = tid & 31;
    int wid = tid >> 5;            // 0..15
    int warpM = wid >> 2;          // 0..3 -> rows warpM*16
    int warpN = wid & 3;           // 0..3 -> cols warpN*32
    int g = lane >> 2;             // 0..7
    int tg = lane & 3;             // 0..3

    // ---- stage W (hi/lo, k-pair packed) ----
    for (int idx = tid; idx < 128 * 128; idx += 512) {
        int kp = idx >> 7, n = idx & 127;
        int k0 = kp * 2, k1 = k0 + 1;
        float w0 = (k0 < F) ? Ws[k0 * F + n] : Wn[(k0 - F) * F + n];
        float w1 = (k1 < F) ? Ws[k1 * F + n] : Wn[(k1 - F) * F + n];
        unsigned hi, lo;
        cvt_pair(w0, w1, hi, lo);
        wW_hi[kp * WW_STRIDE + n] = hi;
        wW_lo[kp * WW_STRIDE + n] = lo;
    }

    int sr = tid >> 3;            // staging row 0..63
    int cb = tid & 7;             // 8 col-blocks of 16 words

    float ls[8], ls2[8];
    #pragma unroll
    for (int i = 0; i < 8; i++) { ls[i] = 0.f; ls2[i] = 0.f; }

    float bcol[8];
    #pragma unroll
    for (int nt = 0; nt < 4; nt++) {
        int col = warpN * 32 + nt * 8 + tg * 2;
        bcol[nt * 2 + 0] = bias[col];
        bcol[nt * 2 + 1] = bias[col + 1];
    }

    for (int tile = blockIdx.x; tile < NTILES; tile += gridDim.x) {
        int nb = tile * 64;
        __syncthreads();

        // ---- stage X tile ----
        {
            int gn = nb + sr;
            unsigned* dhi = sA_hi + sr * SA_STRIDE + cb * 16;
            unsigned* dlo = sA_lo + sr * SA_STRIDE + cb * 16;
            if (gn < NN) {
                if (cb < 4) {
                    // bf16 x: hi = raw packed words, lo = 0
                    const uint4* px = (const uint4*)(x + (size_t)gn * F) + cb * 4;
                    #pragma unroll
                    for (int i = 0; i < 4; i++) {
                        uint4 q = px[i];
                        dhi[i * 4 + 0] = q.x; dhi[i * 4 + 1] = q.y;
                        dhi[i * 4 + 2] = q.z; dhi[i * 4 + 3] = q.w;
                        dlo[i * 4 + 0] = 0u; dlo[i * 4 + 1] = 0u;
                        dlo[i * 4 + 2] = 0u; dlo[i * 4 + 3] = 0u;
                    }
                } else {
                    const float4* pa = (const float4*)(g_agg + (size_t)gn * F) + (cb - 4) * 8;
                    #pragma unroll
                    for (int i = 0; i < 8; i++) {
                        float4 v = pa[i];
                        unsigned h0, l0, h1, l1;
                        cvt_pair(v.x, v.y, h0, l0);
                        cvt_pair(v.z, v.w, h1, l1);
                        dhi[i * 2] = h0; dhi[i * 2 + 1] = h1;
                        dlo[i * 2] = l0; dlo[i * 2 + 1] = l1;
                    }
                }
            } else {
                #pragma unroll
                for (int i = 0; i < 16; i++) { dhi[i] = 0u; dlo[i] = 0u; }
            }
        }
        __syncthreads();

        float c[4][4];
        #pragma unroll
        for (int nt = 0; nt < 4; nt++)
            #pragma unroll
            for (int q = 0; q < 4; q++) c[nt][q] = 0.f;

        int rbase = (warpM * 16 + g) * SA_STRIDE;

        // k < 128: x half, lo(A)==0 -> 2 mma
        #pragma unroll 4
        for (int s = 0; s < 8; s++) {
            int ai = rbase + s * 8 + tg;
            unsigned a0h = sA_hi[ai];
            unsigned a1h = sA_hi[ai + 8 * SA_STRIDE];
            unsigned a2h = sA_hi[ai + 4];
            unsigned a3h = sA_hi[ai + 8 * SA_STRIDE + 4];
            int bi = (s * 8 + tg) * WW_STRIDE + warpN * 32 + g;
            #pragma unroll
            for (int nt = 0; nt < 4; nt++) {
                unsigned b0h = wW_hi[bi + nt * 8];
                unsigned b1h = wW_hi[bi + 4 * WW_STRIDE + nt * 8];
                unsigned b0l = wW_lo[bi + nt * 8];
                unsigned b1l = wW_lo[bi + 4 * WW_STRIDE + nt * 8];
                mma_bf16(c[nt], a0h, a1h, a2h, a3h, b0h, b1h);
                mma_bf16(c[nt], a0h, a1h, a2h, a3h, b0l, b1l);
            }
        }
        // k >= 128: agg half, full 3-product
        #pragma unroll 4
        for (int s = 8; s < 16; s++) {
            int ai = rbase + s * 8 + tg;
            unsigned a0h = sA_hi[ai];
            unsigned a1h = sA_hi[ai + 8 * SA_STRIDE];
            unsigned a2h = sA_hi[ai + 4];
            unsigned a3h = sA_hi[ai + 8 * SA_STRIDE + 4];
            unsigned a0l = sA_lo[ai];
            unsigned a1l = sA_lo[ai + 8 * SA_STRIDE];
            unsigned a2l = sA_lo[ai + 4];
            unsigned a3l = sA_lo[ai + 8 * SA_STRIDE + 4];
            int bi = (s * 8 + tg) * WW_STRIDE + warpN * 32 + g;
            #pragma unroll
            for (int nt = 0; nt < 4; nt++) {
                unsigned b0h = wW_hi[bi + nt * 8];
                unsigned b1h = wW_hi[bi + 4 * WW_STRIDE + nt * 8];
                unsigned b0l = wW_lo[bi + nt * 8];
                unsigned b1l = wW_lo[bi + 4 * WW_STRIDE + nt * 8];
                mma_bf16(c[nt], a0h, a1h, a2h, a3h, b0h, b1h);
                mma_bf16(c[nt], a0h, a1h, a2h, a3h, b0l, b1l);
                mma_bf16(c[nt], a0l, a1l, a2l, a3l, b0h, b1h);
            }
        }

        // ---- epilogue: bias + relu + bf16 store + BN stats (on rounded values) ----
        int r0 = nb + warpM * 16 + g;
        int r1 = r0 + 8;
        #pragma unroll
        for (int nt = 0; nt < 4; nt++) {
            int col = warpN * 32 + nt * 8 + tg * 2;
            float v0 = fmaxf(c[nt][0] + bcol[nt * 2], 0.f);
            float v1 = fmaxf(c[nt][1] + bcol[nt * 2 + 1], 0.f);
            float v2 = fmaxf(c[nt][2] + bcol[nt * 2], 0.f);
            float v3 = fmaxf(c[nt][3] + bcol[nt * 2 + 1], 0.f);
            if (r0 < NN) {
                unsigned pw = (unsigned)__bfloat16_as_ushort(__float2bfloat16(v0))
                            | ((unsigned)__bfloat16_as_ushort(__float2bfloat16(v1)) << 16);
                *(unsigned*)(out + (size_t)r0 * F + col) = pw;
                float q0 = bflo(pw), q1 = bfhi(pw);
                ls[nt * 2] += q0;  ls2[nt * 2] += q0 * q0;
                ls[nt * 2 + 1] += q1; ls2[nt * 2 + 1] += q1 * q1;
            }
            if (r1 < NN) {
                unsigned pw = (unsigned)__bfloat16_as_ushort(__float2bfloat16(v2))
                            | ((unsigned)__bfloat16_as_ushort(__float2bfloat16(v3)) << 16);
                *(unsigned*)(out + (size_t)r1 * F + col) = pw;
                float q0 = bflo(pw), q1 = bfhi(pw);
                ls[nt * 2] += q0;  ls2[nt * 2] += q0 * q0;
                ls[nt * 2 + 1] += q1; ls2[nt * 2 + 1] += q1 * q1;
            }
        }
    }

    // ---- BN stats: smem reduce then one global atomic per column ----
    __syncthreads();
    float* red = (float*)sA_hi;
    for (int i = tid; i < 2 * F; i += 512) red[i] = 0.f;
    __syncthreads();
    #pragma unroll
    for (int nt = 0; nt < 4; nt++) {
        int col = warpN * 32 + nt * 8 + tg * 2;
        atomicAdd(&red[col], ls[nt * 2]);
        atomicAdd(&red[col + 1], ls[nt * 2 + 1]);
        atomicAdd(&red[F + col], ls2[nt * 2]);
        atomicAdd(&red[F + col + 1], ls2[nt * 2 + 1]);
    }
    __syncthreads();
    if (tid < 2 * F) atomicAdd(&sums[tid], red[tid]);
}

// ---------------- batchnorm finalize ----------------
__global__ void k_bnfin(const float* __restrict__ gamma, const float* __restrict__ beta,
                        const float* __restrict__ sums, float* __restrict__ ab) {
    int j = threadIdx.x;
    float invN = 1.0f / (float)NN;
    float mu = sums[j] * invN;
    float var = sums[F + j] * invN - mu * mu;
    float a = gamma[j] * rsqrtf(var + BN_EPS);
    ab[j] = a;
    ab[F + j] = beta[j] - mu * a;
}

// ---------------- apply BN affine + relu in place (bf16) ----------------
// grid*block must be a multiple of 64 so each thread's feature pair is fixed.
__global__ void k_bnapply_b(__nv_bfloat16* __restrict__ h, const float* __restrict__ ab) {
    size_t i = (size_t)blockIdx.x * blockDim.x + threadIdx.x;
    size_t stride = (size_t)gridDim.x * blockDim.x;
    int fp = (int)(i & 63) * 2;
    float a0 = ab[fp], a1 = ab[fp + 1];
    float b0 = ab[F + fp], b1 = ab[F + fp + 1];
    unsigned* hw = (unsigned*)h;
    size_t nw = (size_t)NN * (F / 2);
    for (; i < nw; i += stride) {
        unsigned w = hw[i];
        float f0 = fmaxf(fmaf(bflo(w), a0, b0), 0.f);
        float f1 = fmaxf(fmaf(bfhi(w), a1, b1), 0.f);
        hw[i] = (unsigned)__bfloat16_as_ushort(__float2bfloat16(f0))
              | ((unsigned)__bfloat16_as_ushort(__float2bfloat16(f1)) << 16);
    }
}

// ---------------- final readout: m0 = sum t(h1), m1 = sum w*t(h1) ----------------
__global__ void k_colsum2(const __nv_bfloat16* __restrict__ h) {
    __shared__ float red[2 * F];
    int tid = threadIdx.x;
    int wd = tid & 63;            // word (feature pair)
    int ro = tid >> 6;            // 0..3 row offset
    for (int i = tid; i < 2 * F; i += 256) red[i] = 0.f;
    __syncthreads();
    float s0a = 0.f, s0b = 0.f, s1a = 0.f, s1b = 0.f;
    const unsigned* hw = (const unsigned*)h;
    for (int n = blockIdx.x * 4 + ro; n < NN; n += gridDim.x * 4) {
        unsigned v = hw[(size_t)n * 64 + wd];
        float f0 = bflo(v), f1 = bfhi(v);
        float w = g_w[n];
        s0a += f0; s0b += f1;
        s1a += w * f0; s1b += w * f1;
    }
    atomicAdd(&red[wd * 2], s0a);
    atomicAdd(&red[wd * 2 + 1], s0b);
    atomicAdd(&red[F + wd * 2], s1a);
    atomicAdd(&red[F + wd * 2 + 1], s1b);
    __syncthreads();
    if (tid < 2 * F) atomicAdd(&g_m[tid], red[tid]);
}
__global__ void k_final(const float* __restrict__ Ws2,
                        const float* __restrict__ Wn2,
                        const float* __restrict__ b2,
                        float* __restrict__ out) {
    int o = threadIdx.x;  // 32
    float invN = 1.0f / (float)NN;
    float acc = b2[o];
    #pragma unroll 4
    for (int k = 0; k < F; k++) {
        acc = fmaf(g_m[k] * invN, Ws2[k * OUTD + o], acc);
        acc = fmaf(g_m[F + k] * invN, Wn2[k * OUTD + o], acc);
    }
    float m = acc;
    #pragma unroll
    for (int off = 16; off; off >>= 1)
        m = fmaxf(m, __shfl_xor_sync(0xffffffffu, m, off));
    float e = expf(acc - m);
    float s = e;
    #pragma unroll
    for (int off = 16; off; off >>= 1)
        s += __shfl_xor_sync(0xffffffffu, s, off);
    out[o] = e / s;
}

// ---------------- launch ----------------
extern "C" void kernel_launch(void* const* d_in, const int* in_sizes, int n_in,
                              void* d_out, int out_size) {
    const float* feat = (const float*)d_in[0];
    const int*   src  = (const int*)d_in[1];
    const int*   dst  = (const int*)d_in[2];
    const float* Ws0  = (const float*)d_in[3];
    const float* Wn0  = (const float*)d_in[4];
    const float* b0   = (const float*)d_in[5];
    const float* Ws1  = (const float*)d_in[6];
    const float* Wn1  = (const float*)d_in[7];
    const float* b1   = (const float*)d_in[8];
    const float* Ws2  = (const float*)d_in[9];
    const float* Wn2  = (const float*)d_in[10];
    const float* b2   = (const float*)d_in[11];
    const float* g0   = (const float*)d_in[12];
    const float* be0  = (const float*)d_in[13];
    const float* g1   = (const float*)d_in[14];
    const float* be1  = (const float*)d_in[15];
    float* out = (float*)d_out;

    cudaFuncSetAttribute(k_node, cudaFuncAttributeMaxDynamicSharedMemorySize, SMEM_NODE);

    float *agg, *s0p, *s1p, *ab0, *ab1;
    __nv_bfloat16 *xb, *hb0, *hb1;
    cudaGetSymbolAddress((void**)&agg, g_agg);
    cudaGetSymbolAddress((void**)&xb, g_xb);
    cudaGetSymbolAddress((void**)&hb0, g_hb0);
    cudaGetSymbolAddress((void**)&hb1, g_hb1);
    cudaGetSymbolAddress((void**)&s0p, g_sums0);
    cudaGetSymbolAddress((void**)&s1p, g_sums1);
    cudaGetSymbolAddress((void**)&ab0, g_ab0);
    cudaGetSymbolAddress((void**)&ab1, g_ab1);

    // init + graph preprocessing
    k_zero<<<196, 512>>>();
    k_histcvt<<<HIST_BLOCKS + CVT_BLOCKS, 256>>>(dst, feat);
    k_inv<<<196, 512>>>();
    k_part<<<NCHUNK, 512>>>();
    k_scanp<<<1, 256>>>();
    k_off<<<NCHUNK, 512>>>();
    k_csrw<<<2048, 256>>>(src, dst);

    // ---- layer 0 ----
    k_agg<<<12500, 256>>>(xb, agg);
    k_node<<<148, 512, SMEM_NODE>>>(xb, Ws0, Wn0, b0, hb0, s0p);
    k_bnfin<<<1, 128>>>(g0, be0, s0p, ab0);
    k_bnapply_b<<<1024, 256>>>(hb0, ab0);

    // ---- layer 1 ----
    k_agg<<<12500, 256>>>(hb0, agg);
    k_node<<<148, 512, SMEM_NODE>>>(hb0, Ws1, Wn1, b1, hb1, s1p);
    k_bnfin<<<1, 128>>>(g1, be1, s1p, ab1);
    k_bnapply_b<<<1024, 256>>>(hb1, ab1);

    // ---- layer 2 folded into readout ----
    k_colsum2<<<512, 256>>>(hb1);
    k_final<<<1, 32>>>(Ws2, Wn2, b2, out);
}

// round 7
// speedup vs baseline: 6.1880x; 1.1734x over previous
#include <cuda_runtime.h>
#include <cuda_bf16.h>
#include <math.h>

#define NN   100000
#define NE   1600000
#define F    128
#define OUTD 32
#define BN_EPS 1e-5f
#define NCHUNK 196   // 196*512 = 100352 >= NN

// ---------------- scratch (device globals; no allocation allowed) ----------------
__device__ int   g_degi[NN];
__device__ float g_inv[NN];
__device__ float g_w[NN];          // w[s] = sum over edges with src==s of inv_deg[dst]
__device__ int   g_off[NN + 1];
__device__ int   g_cur[NN];
__device__ int   g_csr[NE];
__device__ int   g_part[NCHUNK];
__device__ __nv_bfloat16 g_aggb[(size_t)NN * F]; // aggregated bf16 (scaled by inv_deg)
__device__ __nv_bfloat16 g_xb[(size_t)NN * F];   // bf16 features
__device__ __nv_bfloat16 g_hb0[(size_t)NN * F];  // bf16 layer outputs
__device__ __nv_bfloat16 g_hb1[(size_t)NN * F];
__device__ float g_sums0[2 * F];
__device__ float g_sums1[2 * F];
__device__ float g_ab0[2 * F];     // BN affine: [0:F) scale a, [F:2F) shift b
__device__ float g_ab1[2 * F];
__device__ float g_m[2 * F];       // [0:F) sum t(h1), [F:2F) sum w*t(h1)

__device__ __forceinline__ float bflo(unsigned w) { return __uint_as_float(w << 16); }
__device__ __forceinline__ float bfhi(unsigned w) { return __uint_as_float(w & 0xffff0000u); }
__device__ __forceinline__ unsigned bfpack(float a, float b) {
    return (unsigned)__bfloat16_as_ushort(__float2bfloat16(a))
         | ((unsigned)__bfloat16_as_ushort(__float2bfloat16(b)) << 16);
}

// ---------------- init ----------------
__global__ void k_zero() {
    int i = blockIdx.x * blockDim.x + threadIdx.x;
    int stride = gridDim.x * blockDim.x;
    for (; i < NN; i += stride) { g_degi[i] = 0; g_cur[i] = 0; g_w[i] = 0.0f; }
    if (blockIdx.x == 0 && threadIdx.x < 2 * F) {
        g_sums0[threadIdx.x] = 0.0f;
        g_sums1[threadIdx.x] = 0.0f;
        g_m[threadIdx.x] = 0.0f;
    }
}

// ---------------- fused: degree histogram + feat->bf16 conversion ----------------
#define HIST_BLOCKS 2048
#define CVT_BLOCKS  1552
__global__ void k_histcvt(const int* __restrict__ dst, const float* __restrict__ feat) {
    if (blockIdx.x < HIST_BLOCKS) {
        int i = blockIdx.x * 256 + threadIdx.x;
        int stride = HIST_BLOCKS * 256;
        for (; i < NE; i += stride) atomicAdd(&g_degi[dst[i]], 1);
    } else {
        size_t i = (size_t)(blockIdx.x - HIST_BLOCKS) * 256 + threadIdx.x;
        size_t stride = (size_t)CVT_BLOCKS * 256;
        size_t np = (size_t)NN * F / 2;
        const float2* src2 = (const float2*)feat;
        unsigned* dst2 = (unsigned*)g_xb;
        for (; i < np; i += stride) {
            float2 v = src2[i];
            dst2[i] = bfpack(v.x, v.y);
        }
    }
}

// ---------------- CSR build (k_part also computes inv_deg) ----------------
__global__ void k_part() {
    __shared__ int sh[512];
    int c = blockIdx.x, t = threadIdx.x;
    int i = c * 512 + t;
    int v = (i < NN) ? g_degi[i] : 0;
    if (i < NN) g_inv[i] = 1.0f / fmaxf((float)v, 1.0f);
    sh[t] = v;
    __syncthreads();
    for (int s = 256; s > 0; s >>= 1) {
        if (t < s) sh[t] += sh[t + s];
        __syncthreads();
    }
    if (t == 0) g_part[c] = sh[0];
}
__global__ void k_scanp() {
    __shared__ int sh[256];
    int t = threadIdx.x;
    sh[t] = (t < NCHUNK) ? g_part[t] : 0;
    __syncthreads();
    for (int d = 1; d < 256; d <<= 1) {
        int v = (t >= d) ? sh[t - d] : 0;
        __syncthreads();
        sh[t] += v;
        __syncthreads();
    }
    if (t < NCHUNK) g_part[t] = (t == 0) ? 0 : sh[t - 1];  // exclusive
    if (t == 0) g_off[NN] = NE;
}
__global__ void k_off() {
    __shared__ int sh[512];
    int c = blockIdx.x, t = threadIdx.x;
    int i = c * 512 + t;
    int v = (i < NN) ? g_degi[i] : 0;
    sh[t] = v;
    __syncthreads();
    for (int d = 1; d < 512; d <<= 1) {
        int u = (t >= d) ? sh[t - d] : 0;
        __syncthreads();
        sh[t] += u;
        __syncthreads();
    }
    if (i < NN) g_off[i] = g_part[c] + (sh[t] - v);
}
// merged CSR fill + src-weight accumulation (one edge pass)
__global__ void k_csrw(const int* __restrict__ src, const int* __restrict__ dst) {
    int i = blockIdx.x * blockDim.x + threadIdx.x;
    int stride = gridDim.x * blockDim.x;
    for (; i < NE; i += stride) {
        int d = dst[i];
        int s = src[i];
        float iv = g_inv[d];
        int p = atomicAdd(&g_cur[d], 1);
        g_csr[g_off[d] + p] = s;
        atomicAdd(&g_w[s], iv);
    }
}

// ---------------- CSR aggregation: aggb[n] = bf16( inv[n] * sum x[s] ) ----------------
__global__ void k_agg(const __nv_bfloat16* __restrict__ x) {
    int lane = threadIdx.x & 31;
    int warp = (blockIdx.x * blockDim.x + threadIdx.x) >> 5;
    int nwarp = (gridDim.x * blockDim.x) >> 5;
    for (int n = warp; n < NN; n += nwarp) {
        int e0 = g_off[n], e1 = g_off[n + 1];
        float4 acc = make_float4(0.f, 0.f, 0.f, 0.f);
        int e = e0;
        for (; e + 1 < e1; e += 2) {
            int s0 = g_csr[e], s1 = g_csr[e + 1];
            uint2 v0 = ((const uint2*)(x + (size_t)s0 * F))[lane];
            uint2 v1 = ((const uint2*)(x + (size_t)s1 * F))[lane];
            acc.x += bflo(v0.x) + bflo(v1.x);
            acc.y += bfhi(v0.x) + bfhi(v1.x);
            acc.z += bflo(v0.y) + bflo(v1.y);
            acc.w += bfhi(v0.y) + bfhi(v1.y);
        }
        if (e < e1) {
            int s0 = g_csr[e];
            uint2 v0 = ((const uint2*)(x + (size_t)s0 * F))[lane];
            acc.x += bflo(v0.x); acc.y += bfhi(v0.x);
            acc.z += bflo(v0.y); acc.w += bfhi(v0.y);
        }
        float w = g_inv[n];
        uint2 o = make_uint2(bfpack(acc.x * w, acc.y * w), bfpack(acc.z * w, acc.w * w));
        ((uint2*)(g_aggb + (size_t)n * F))[lane] = o;
    }
}

// ================= tensor-core node update ==============================
// C[64 x 128] = X[64 x 256] @ W[256 x 128],  X = [x_bf16 | agg_bf16],  W = [Ws; Wn]
// weights split-bf16 (hi+lo); X is plain bf16 -> 2 mma per k-step.
// W smem layout is nt-permuted: within each 32-col warp tile, col c is stored at
// word (c&7)*4 + (c>>3), so one LDS.128 fetches a thread's 4 nt-columns.
#define WW_STRIDE 136
#define SA_STRIDE 132
#define OFF_WLO  (128 * WW_STRIDE)
#define OFF_AHI  (2 * 128 * WW_STRIDE)
#define SMEM_WORDS (2 * 128 * WW_STRIDE + 64 * SA_STRIDE)
#define SMEM_NODE (SMEM_WORDS * 4)
#define NTILES ((NN + 63) / 64)

__device__ __forceinline__ void cvt_pair(float vx, float vy, unsigned& hi, unsigned& lo) {
    __nv_bfloat16 hx = __float2bfloat16(vx);
    __nv_bfloat16 hy = __float2bfloat16(vy);
    __nv_bfloat16 lx = __float2bfloat16(vx - __bfloat162float(hx));
    __nv_bfloat16 ly = __float2bfloat16(vy - __bfloat162float(hy));
    hi = (unsigned)__bfloat16_as_ushort(hx) | ((unsigned)__bfloat16_as_ushort(hy) << 16);
    lo = (unsigned)__bfloat16_as_ushort(lx) | ((unsigned)__bfloat16_as_ushort(ly) << 16);
}

__device__ __forceinline__ void mma_bf16(float* c, unsigned a0, unsigned a1, unsigned a2,
                                         unsigned a3, unsigned b0, unsigned b1) {
    asm volatile(
        "mma.sync.aligned.m16n8k16.row.col.f32.bf16.bf16.f32 "
        "{%0,%1,%2,%3}, {%4,%5,%6,%7}, {%8,%9}, {%0,%1,%2,%3};"
        : "+f"(c[0]), "+f"(c[1]), "+f"(c[2]), "+f"(c[3])
        : "r"(a0), "r"(a1), "r"(a2), "r"(a3), "r"(b0), "r"(b1));
}

__global__ void __launch_bounds__(512, 1)
k_node(const __nv_bfloat16* __restrict__ x,
       const float* __restrict__ Ws,
       const float* __restrict__ Wn,
       const float* __restrict__ bias,
       __nv_bfloat16* __restrict__ out,
       float* __restrict__ sums) {      // [2F] BN stats accumulator
    extern __shared__ unsigned sm[];
    unsigned* wW_hi = sm;
    unsigned* wW_lo = sm + OFF_WLO;
    unsigned* sA_hi = sm + OFF_AHI;

    int tid = threadIdx.x;
    int lane = tid & 31;
    int wid = tid >> 5;            // 0..15
    int warpM = wid >> 2;          // 0..3 -> rows warpM*16
    int warpN = wid & 3;           // 0..3 -> cols warpN*32
    int g = lane >> 2;             // 0..7
    int tg = lane & 3;             // 0..3

    // ---- stage W (hi/lo, k-pair packed, nt-permuted within 32-col groups) ----
    for (int idx = tid; idx < 128 * 128; idx += 512) {
        int kp = idx >> 7, n = idx & 127;
        int k0 = kp * 2, k1 = k0 + 1;
        float w0 = (k0 < F) ? Ws[k0 * F + n] : Wn[(k0 - F) * F + n];
        float w1 = (k1 < F) ? Ws[k1 * F + n] : Wn[(k1 - F) * F + n];
        unsigned hi, lo;
        cvt_pair(w0, w1, hi, lo);
        int c = n & 31;
        int pos = kp * WW_STRIDE + (n & ~31) + ((c & 7) << 2) + (c >> 3);
        wW_hi[pos] = hi;
        wW_lo[pos] = lo;
    }

    int sr = tid >> 3;            // staging row 0..63
    int cb = tid & 7;             // 8 col-blocks of 16 words

    float ls[8], ls2[8];
    #pragma unroll
    for (int i = 0; i < 8; i++) { ls[i] = 0.f; ls2[i] = 0.f; }

    float bcol[8];
    #pragma unroll
    for (int nt = 0; nt < 4; nt++) {
        int col = warpN * 32 + nt * 8 + tg * 2;
        bcol[nt * 2 + 0] = bias[col];
        bcol[nt * 2 + 1] = bias[col + 1];
    }

    for (int tile = blockIdx.x; tile < NTILES; tile += gridDim.x) {
        int nb = tile * 64;
        __syncthreads();

        // ---- stage X tile (raw bf16 copies; x half then agg half) ----
        {
            int gn = nb + sr;
            unsigned* dhi = sA_hi + sr * SA_STRIDE + cb * 16;
            if (gn < NN) {
                const uint4* p = (cb < 4)
                    ? ((const uint4*)(x + (size_t)gn * F) + cb * 4)
                    : ((const uint4*)(g_aggb + (size_t)gn * F) + (cb - 4) * 4);
                #pragma unroll
                for (int i = 0; i < 4; i++) {
                    uint4 q = p[i];
                    dhi[i * 4 + 0] = q.x; dhi[i * 4 + 1] = q.y;
                    dhi[i * 4 + 2] = q.z; dhi[i * 4 + 3] = q.w;
                }
            } else {
                #pragma unroll
                for (int i = 0; i < 16; i++) dhi[i] = 0u;
            }
        }
        __syncthreads();

        float c[4][4];
        #pragma unroll
        for (int nt = 0; nt < 4; nt++)
            #pragma unroll
            for (int q = 0; q < 4; q++) c[nt][q] = 0.f;

        int rbase = (warpM * 16 + g) * SA_STRIDE;

        #pragma unroll 4
        for (int s = 0; s < 16; s++) {
            int ai = rbase + s * 8 + tg;
            unsigned a0h = sA_hi[ai];
            unsigned a1h = sA_hi[ai + 8 * SA_STRIDE];
            unsigned a2h = sA_hi[ai + 4];
            unsigned a3h = sA_hi[ai + 8 * SA_STRIDE + 4];
            int bi = (s * 8 + tg) * WW_STRIDE + warpN * 32 + g * 4;
            uint4 b0h = *(const uint4*)(wW_hi + bi);
            uint4 b1h = *(const uint4*)(wW_hi + bi + 4 * WW_STRIDE);
            uint4 b0l = *(const uint4*)(wW_lo + bi);
            uint4 b1l = *(const uint4*)(wW_lo + bi + 4 * WW_STRIDE);
            mma_bf16(c[0], a0h, a1h, a2h, a3h, b0h.x, b1h.x);
            mma_bf16(c[0], a0h, a1h, a2h, a3h, b0l.x, b1l.x);
            mma_bf16(c[1], a0h, a1h, a2h, a3h, b0h.y, b1h.y);
            mma_bf16(c[1], a0h, a1h, a2h, a3h, b0l.y, b1l.y);
            mma_bf16(c[2], a0h, a1h, a2h, a3h, b0h.z, b1h.z);
            mma_bf16(c[2], a0h, a1h, a2h, a3h, b0l.z, b1l.z);
            mma_bf16(c[3], a0h, a1h, a2h, a3h, b0h.w, b1h.w);
            mma_bf16(c[3], a0h, a1h, a2h, a3h, b0l.w, b1l.w);
        }

        // ---- epilogue: bias + relu + bf16 store + BN stats (on rounded values) ----
        int r0 = nb + warpM * 16 + g;
        int r1 = r0 + 8;
        #pragma unroll
        for (int nt = 0; nt < 4; nt++) {
            int col = warpN * 32 + nt * 8 + tg * 2;
            float v0 = fmaxf(c[nt][0] + bcol[nt * 2], 0.f);
            float v1 = fmaxf(c[nt][1] + bcol[nt * 2 + 1], 0.f);
            float v2 = fmaxf(c[nt][2] + bcol[nt * 2], 0.f);
            float v3 = fmaxf(c[nt][3] + bcol[nt * 2 + 1], 0.f);
            if (r0 < NN) {
                unsigned pw = bfpack(v0, v1);
                *(unsigned*)(out + (size_t)r0 * F + col) = pw;
                float q0 = bflo(pw), q1 = bfhi(pw);
                ls[nt * 2] += q0;  ls2[nt * 2] += q0 * q0;
                ls[nt * 2 + 1] += q1; ls2[nt * 2 + 1] += q1 * q1;
            }
            if (r1 < NN) {
                unsigned pw = bfpack(v2, v3);
                *(unsigned*)(out + (size_t)r1 * F + col) = pw;
                float q0 = bflo(pw), q1 = bfhi(pw);
                ls[nt * 2] += q0;  ls2[nt * 2] += q0 * q0;
                ls[nt * 2 + 1] += q1; ls2[nt * 2 + 1] += q1 * q1;
            }
        }
    }

    // ---- BN stats: smem reduce then one global atomic per column ----
    __syncthreads();
    float* red = (float*)sA_hi;
    for (int i = tid; i < 2 * F; i += 512) red[i] = 0.f;
    __syncthreads();
    #pragma unroll
    for (int nt = 0; nt < 4; nt++) {
        int col = warpN * 32 + nt * 8 + tg * 2;
        atomicAdd(&red[col], ls[nt * 2]);
        atomicAdd(&red[col + 1], ls[nt * 2 + 1]);
        atomicAdd(&red[F + col], ls2[nt * 2]);
        atomicAdd(&red[F + col + 1], ls2[nt * 2 + 1]);
    }
    __syncthreads();
    if (tid < 2 * F) atomicAdd(&sums[tid], red[tid]);
}

// ---------------- batchnorm finalize ----------------
__global__ void k_bnfin(const float* __restrict__ gamma, const float* __restrict__ beta,
                        const float* __restrict__ sums, float* __restrict__ ab) {
    int j = threadIdx.x;
    float invN = 1.0f / (float)NN;
    float mu = sums[j] * invN;
    float var = sums[F + j] * invN - mu * mu;
    float a = gamma[j] * rsqrtf(var + BN_EPS);
    ab[j] = a;
    ab[F + j] = beta[j] - mu * a;
}

// ---------------- apply BN affine + relu in place (bf16) ----------------
__global__ void k_bnapply_b(__nv_bfloat16* __restrict__ h, const float* __restrict__ ab) {
    size_t i = (size_t)blockIdx.x * blockDim.x + threadIdx.x;
    size_t stride = (size_t)gridDim.x * blockDim.x;
    int fp = (int)(i & 63) * 2;
    float a0 = ab[fp], a1 = ab[fp + 1];
    float b0 = ab[F + fp], b1 = ab[F + fp + 1];
    unsigned* hw = (unsigned*)h;
    size_t nw = (size_t)NN * (F / 2);
    for (; i < nw; i += stride) {
        unsigned w = hw[i];
        float f0 = fmaxf(fmaf(bflo(w), a0, b0), 0.f);
        float f1 = fmaxf(fmaf(bfhi(w), a1, b1), 0.f);
        hw[i] = bfpack(f0, f1);
    }
}

// ---------------- final readout: m0 = sum t(h1), m1 = sum w*t(h1) ----------------
// BN1 affine + relu fused here (h1 is raw pre-BN output).
__global__ void k_colsum2(const __nv_bfloat16* __restrict__ h, const float* __restrict__ ab) {
    __shared__ float red[2 * F];
    int tid = threadIdx.x;
    int wd = tid & 63;            // word (feature pair)
    int ro = tid >> 6;            // 0..3 row offset
    float a0 = ab[wd * 2], a1 = ab[wd * 2 + 1];
    float b0 = ab[F + wd * 2], b1 = ab[F + wd * 2 + 1];
    for (int i = tid; i < 2 * F; i += 256) red[i] = 0.f;
    __syncthreads();
    float s0a = 0.f, s0b = 0.f, s1a = 0.f, s1b = 0.f;
    const unsigned* hw = (const unsigned*)h;
    for (int n = blockIdx.x * 4 + ro; n < NN; n += gridDim.x * 4) {
        unsigned v = hw[(size_t)n * 64 + wd];
        float f0 = fmaxf(fmaf(bflo(v), a0, b0), 0.f);
        float f1 = fmaxf(fmaf(bfhi(v), a1, b1), 0.f);
        float w = g_w[n];
        s0a += f0; s0b += f1;
        s1a += w * f0; s1b += w * f1;
    }
    atomicAdd(&red[wd * 2], s0a);
    atomicAdd(&red[wd * 2 + 1], s0b);
    atomicAdd(&red[F + wd * 2], s1a);
    atomicAdd(&red[F + wd * 2 + 1], s1b);
    __syncthreads();
    if (tid < 2 * F) atomicAdd(&g_m[tid], red[tid]);
}
__global__ void k_final(const float* __restrict__ Ws2,
                        const float* __restrict__ Wn2,
                        const float* __restrict__ b2,
                        float* __restrict__ out) {
    int o = threadIdx.x;  // 32
    float invN = 1.0f / (float)NN;
    float acc = b2[o];
    #pragma unroll 4
    for (int k = 0; k < F; k++) {
        acc = fmaf(g_m[k] * invN, Ws2[k * OUTD + o], acc);
        acc = fmaf(g_m[F + k] * invN, Wn2[k * OUTD + o], acc);
    }
    float m = acc;
    #pragma unroll
    for (int off = 16; off; off >>= 1)
        m = fmaxf(m, __shfl_xor_sync(0xffffffffu, m, off));
    float e = expf(acc - m);
    float s = e;
    #pragma unroll
    for (int off = 16; off; off >>= 1)
        s += __shfl_xor_sync(0xffffffffu, s, off);
    out[o] = e / s;
}

// ---------------- launch ----------------
extern "C" void kernel_launch(void* const* d_in, const int* in_sizes, int n_in,
                              void* d_out, int out_size) {
    const float* feat = (const float*)d_in[0];
    const int*   src  = (const int*)d_in[1];
    const int*   dst  = (const int*)d_in[2];
    const float* Ws0  = (const float*)d_in[3];
    const float* Wn0  = (const float*)d_in[4];
    const float* b0   = (const float*)d_in[5];
    const float* Ws1  = (const float*)d_in[6];
    const float* Wn1  = (const float*)d_in[7];
    const float* b1   = (const float*)d_in[8];
    const float* Ws2  = (const float*)d_in[9];
    const float* Wn2  = (const float*)d_in[10];
    const float* b2   = (const float*)d_in[11];
    const float* g0   = (const float*)d_in[12];
    const float* be0  = (const float*)d_in[13];
    const float* g1   = (const float*)d_in[14];
    const float* be1  = (const float*)d_in[15];
    float* out = (float*)d_out;

    cudaFuncSetAttribute(k_node, cudaFuncAttributeMaxDynamicSharedMemorySize, SMEM_NODE);

    float *s0p, *s1p, *ab0, *ab1;
    __nv_bfloat16 *xb, *hb0, *hb1;
    cudaGetSymbolAddress((void**)&xb, g_xb);
    cudaGetSymbolAddress((void**)&hb0, g_hb0);
    cudaGetSymbolAddress((void**)&hb1, g_hb1);
    cudaGetSymbolAddress((void**)&s0p, g_sums0);
    cudaGetSymbolAddress((void**)&s1p, g_sums1);
    cudaGetSymbolAddress((void**)&ab0, g_ab0);
    cudaGetSymbolAddress((void**)&ab1, g_ab1);

    // init + graph preprocessing
    k_zero<<<196, 512>>>();
    k_histcvt<<<HIST_BLOCKS + CVT_BLOCKS, 256>>>(dst, feat);
    k_part<<<NCHUNK, 512>>>();
    k_scanp<<<1, 256>>>();
    k_off<<<NCHUNK, 512>>>();
    k_csrw<<<2048, 256>>>(src, dst);

    // ---- layer 0 ----
    k_agg<<<12500, 256>>>(xb);
    k_node<<<148, 512, SMEM_NODE>>>(xb, Ws0, Wn0, b0, hb0, s0p);
    k_bnfin<<<1, 128>>>(g0, be0, s0p, ab0);
    k_bnapply_b<<<1024, 256>>>(hb0, ab0);

    // ---- layer 1 ----
    k_agg<<<12500, 256>>>(hb0);
    k_node<<<148, 512, SMEM_NODE>>>(hb0, Ws1, Wn1, b1, hb1, s1p);
    k_bnfin<<<1, 128>>>(g1, be1, s1p, ab1);

    // ---- layer 2 folded into readout (BN1 fused into colsum) ----
    k_colsum2<<<512, 256>>>(hb1, ab1);
    k_final<<<1, 32>>>(Ws2, Wn2, b2, out);
}